// round 8
// baseline (speedup 1.0000x reference)
#include <cuda_runtime.h>
#include <cstdint>

// OneHotEncoder: per-row token histogram (skip pad_idx=0) -> float counts.
// tokens: [B, T] int32, out: [B, 32000] float32.
//
// R8: issue-bound analysis (R7: 25K issued slots/SM ~= scan cost) -> cut
// instructions per token-inspection and max out warp residency:
//  - pad check folded into the range check: for slice s>0,
//    (unsigned)(t-lo) < BINS already excludes t==0; for s==0 use
//    (unsigned)(t-1) < BINS-1 with a +1-biased hist pointer. One IADD3 +
//    one ISETP + predicated ATOMS per token (~3 slots vs ~5).
//  - 512 threads/CTA, 1 int4/thread: 4 CTAs x 512thr = 64 warps/SM (full
//    occupancy) at 64KB smem.
// Kept from R7: SPLIT=8 (16KB f32 slice hist), register token prefetch
// before the smem-zero loop, single TMA 1-D bulk store per slice.
// fp32 smem atomicAdd is exact for integer counts. Column 0 stays zero.

constexpr int VOCAB    = 32000;
constexpr int SPLIT    = 8;
constexpr int BINS     = VOCAB / SPLIT;   // 4000 floats = 16000 B per slice
constexpr int NTHREADS = 512;

__global__ __launch_bounds__(NTHREADS, 4)
void onehot_hist_tma_kernel(const int4* __restrict__ tokens4,
                            float* __restrict__ out,
                            int vecs_per_row)   // T/4 = 512
{
    extern __shared__ float hist[];   // BINS floats = 16000 B

    const int cta = blockIdx.x;
    const int s   = cta & (SPLIT - 1);       // vocab slice index
    const int b   = cta >> 3;                // row index
    const int lo  = s * BINS;
    const int tid = threadIdx.x;

    // Pad-fold: for s==0 shift the window by 1 so t==0 fails the single
    // range check; bias the hist pointer back so bin indices still match.
    const int      adj    = (s == 0) ? 1 : 0;
    const int      loAdj  = lo + adj;
    const unsigned range  = (unsigned)(BINS - adj);
    float* __restrict__ histAdj = hist + adj;

    // Prefetch this thread's int4 of tokens (front-batched LDG) so the L2
    // load latency hides behind the smem-zero loop.
    const int4* __restrict__ trow = tokens4 + (size_t)b * vecs_per_row;
    int4 t = (tid < vecs_per_row) ? trow[tid] : make_int4(0, 0, 0, 0);

    // Zero the slice histogram (1000 float4 over 512 threads).
    float4 z = make_float4(0.f, 0.f, 0.f, 0.f);
    #pragma unroll
    for (int i = tid; i < BINS / 4; i += NTHREADS) {
        reinterpret_cast<float4*>(hist)[i] = z;
    }
    __syncthreads();

    // Count tokens in this slice: one sub + one unsigned compare per token,
    // then a predicated smem atomic.
    {
        unsigned x;
        x = (unsigned)(t.x - loAdj); if (x < range) atomicAdd(&histAdj[x], 1.0f);
        x = (unsigned)(t.y - loAdj); if (x < range) atomicAdd(&histAdj[x], 1.0f);
        x = (unsigned)(t.z - loAdj); if (x < range) atomicAdd(&histAdj[x], 1.0f);
        x = (unsigned)(t.w - loAdj); if (x < range) atomicAdd(&histAdj[x], 1.0f);
    }
    __syncthreads();

    // One TMA 1-D bulk store writes the whole 16000B slice to global.
    if (tid == 0) {
        asm volatile("fence.proxy.async.shared::cta;" ::: "memory");
        uint32_t saddr = (uint32_t)__cvta_generic_to_shared(hist);
        float* gdst = out + (size_t)b * VOCAB + lo;   // 16B-aligned slices
        asm volatile(
            "cp.async.bulk.global.shared::cta.bulk_group [%0], [%1], %2;"
            :: "l"(gdst), "r"(saddr), "r"((unsigned)(BINS * sizeof(float)))
            : "memory");
        asm volatile("cp.async.bulk.commit_group;" ::: "memory");
        asm volatile("cp.async.bulk.wait_group 0;" ::: "memory");
    }
}

extern "C" void kernel_launch(void* const* d_in, const int* in_sizes, int n_in,
                              void* d_out, int out_size)
{
    const int* tokens = (const int*)d_in[0];   // [B, T] int32
    // d_in[1] = lengths [B] int32 — unused by the reference computation.

    const int B = in_sizes[1];                 // 256
    const int T = in_sizes[0] / B;             // 2048

    float* out = (float*)d_out;                // [B, VOCAB] float32

    const int smem_bytes = BINS * (int)sizeof(float);  // 16000
    cudaFuncSetAttribute(onehot_hist_tma_kernel,
                         cudaFuncAttributeMaxDynamicSharedMemorySize,
                         smem_bytes);
    cudaFuncSetAttribute(onehot_hist_tma_kernel,
                         cudaFuncAttributePreferredSharedMemoryCarveout,
                         cudaSharedmemCarveoutMaxShared);

    onehot_hist_tma_kernel<<<B * SPLIT, NTHREADS, smem_bytes>>>(
        (const int4*)tokens, out, T / 4);
}

// round 9
// speedup vs baseline: 1.0030x; 1.0030x over previous
#include <cuda_runtime.h>
#include <cstdint>

// OneHotEncoder: per-row token histogram (skip pad_idx=0) -> float counts.
// tokens: [B, T] int32, out: [B, 32000] float32.
//
// R9: double-buffered 2-row pipeline per CTA. The smem family's port budget
// (~11K cyc/SM: STS-zero + ATOMS + TMA smem-read) implies a ~5.5us floor,
// but R8 ran 10.3us because every CTA serialized zero->atomics->TMA-wait and
// retired (2048 launch/drain critical paths). Here each CTA handles 2 rows
// with two 16KB f32 slice histograms:
//   prefetch both rows' tokens (MLP=4) ->
//   zero A -> atomics row0 -> commit TMA(A) [no wait] ->
//   zero B -> atomics row1 -> commit TMA(B) -> wait_group 0 once.
// TMA(A) drains under row1's compute. 1024 CTAs x 256thr x 32KB -> ~7/SM.
// fp32 smem atomicAdd is exact for integer counts; pad check folded into
// the unsigned range check (+1 bias on slice 0). Column 0 stays zero.

constexpr int VOCAB    = 32000;
constexpr int SPLIT    = 8;
constexpr int BINS     = VOCAB / SPLIT;   // 4000 floats = 16000 B per slice
constexpr int NTHREADS = 256;
constexpr int VPT      = 2;               // int4 per thread per row (T=2048)
constexpr int ROWS_PER_CTA = 2;

__device__ __forceinline__ void tma_store_slice(float* gdst, const float* sbuf)
{
    asm volatile("fence.proxy.async.shared::cta;" ::: "memory");
    uint32_t saddr = (uint32_t)__cvta_generic_to_shared(sbuf);
    asm volatile(
        "cp.async.bulk.global.shared::cta.bulk_group [%0], [%1], %2;"
        :: "l"(gdst), "r"(saddr), "r"((unsigned)(BINS * sizeof(float)))
        : "memory");
    asm volatile("cp.async.bulk.commit_group;" ::: "memory");
}

__global__ __launch_bounds__(NTHREADS)
void onehot_hist_pipe_kernel(const int4* __restrict__ tokens4,
                             float* __restrict__ out,
                             int vecs_per_row)   // T/4 = 512
{
    extern __shared__ float hist[];   // 2 * BINS floats (double buffer)

    const int cta = blockIdx.x;
    const int s   = cta & (SPLIT - 1);              // vocab slice
    const int b0  = (cta >> 3) * ROWS_PER_CTA;      // first row
    const int lo  = s * BINS;
    const int tid = threadIdx.x;

    // Pad-fold: on slice 0 shift the window by 1 so t==0 fails the single
    // unsigned range check; bias the hist pointer back to compensate.
    const int      adj   = (s == 0) ? 1 : 0;
    const int      loAdj = lo + adj;
    const unsigned range = (unsigned)(BINS - adj);

    // Front-batched prefetch of BOTH rows' tokens (4 x LDG.128, MLP=4).
    int4 tv[ROWS_PER_CTA][VPT];
    #pragma unroll
    for (int r = 0; r < ROWS_PER_CTA; r++) {
        const int4* __restrict__ trow = tokens4 + (size_t)(b0 + r) * vecs_per_row;
        #pragma unroll
        for (int v = 0; v < VPT; v++) {
            int i = tid + v * NTHREADS;
            tv[r][v] = trow[i];
        }
    }

    float4 z = make_float4(0.f, 0.f, 0.f, 0.f);

    #pragma unroll
    for (int r = 0; r < ROWS_PER_CTA; r++) {
        float* __restrict__ buf = hist + r * BINS;

        // Zero this row's buffer (1000 float4 over 256 threads).
        #pragma unroll
        for (int i = tid; i < BINS / 4; i += NTHREADS) {
            reinterpret_cast<float4*>(buf)[i] = z;
        }
        __syncthreads();

        // Count tokens in this slice: sub + unsigned cmp + predicated ATOMS.
        float* __restrict__ bufAdj = buf + adj;
        #pragma unroll
        for (int v = 0; v < VPT; v++) {
            int4 t = tv[r][v];
            unsigned x;
            x = (unsigned)(t.x - loAdj); if (x < range) atomicAdd(&bufAdj[x], 1.0f);
            x = (unsigned)(t.y - loAdj); if (x < range) atomicAdd(&bufAdj[x], 1.0f);
            x = (unsigned)(t.z - loAdj); if (x < range) atomicAdd(&bufAdj[x], 1.0f);
            x = (unsigned)(t.w - loAdj); if (x < range) atomicAdd(&bufAdj[x], 1.0f);
        }
        __syncthreads();

        // Commit the TMA bulk store; do NOT wait here — the next row's
        // zero/atomics (other buffer) overlap this store's drain.
        if (tid == 0) {
            tma_store_slice(out + (size_t)(b0 + r) * VOCAB + lo, buf);
        }
        // No barrier needed: next iteration touches only the other buffer,
        // and its pre-atomics __syncthreads orders everything that matters.
    }

    // Drain both stores before CTA exit.
    if (tid == 0) {
        asm volatile("cp.async.bulk.wait_group 0;" ::: "memory");
    }
}

extern "C" void kernel_launch(void* const* d_in, const int* in_sizes, int n_in,
                              void* d_out, int out_size)
{
    const int* tokens = (const int*)d_in[0];   // [B, T] int32
    // d_in[1] = lengths [B] int32 — unused by the reference computation.

    const int B = in_sizes[1];                 // 256
    const int T = in_sizes[0] / B;             // 2048

    float* out = (float*)d_out;                // [B, VOCAB] float32

    const int smem_bytes = 2 * BINS * (int)sizeof(float);  // 32000
    cudaFuncSetAttribute(onehot_hist_pipe_kernel,
                         cudaFuncAttributeMaxDynamicSharedMemorySize,
                         smem_bytes);
    cudaFuncSetAttribute(onehot_hist_pipe_kernel,
                         cudaFuncAttributePreferredSharedMemoryCarveout,
                         cudaSharedmemCarveoutMaxShared);

    const int grid = (B / ROWS_PER_CTA) * SPLIT;   // 1024
    onehot_hist_pipe_kernel<<<grid, NTHREADS, smem_bytes>>>(
        (const int4*)tokens, out, T / 4);
}